// round 13
// baseline (speedup 1.0000x reference)
#include <cuda_runtime.h>
#include <cuda_bf16.h>
#include <cuda_fp16.h>

#define N_NODES 50000
#define N_EDGES 800000
#define D 64
#define NBLK ((N_NODES + 255) / 256)   // 196

// ---------------------------------------------------------------------------
// Static device scratch. g_cnt zero at load; scatter_idx re-zeroes it each
// run (after scanfin has consumed it) -> graph-replay deterministic.
// ---------------------------------------------------------------------------
__device__ int    g_cnt[N_NODES];
__device__ int    g_offs[N_NODES + 1];
__device__ int    g_cursor[N_NODES];
__device__ int    g_sorted[N_EDGES];
__device__ float  g_Y[N_NODES * D];            // Y = feat @ W^T (fp32)
__device__ __half g_Yh[N_NODES * D];           // fp16 copy for gather traffic

// Side stream + events for graph-forked overlap (created at program init).
static cudaStream_t g_side;
static cudaEvent_t  g_evFork, g_evJoin;
namespace {
struct _Init {
    _Init() {
        cudaStreamCreateWithFlags(&g_side, cudaStreamNonBlocking);
        cudaEventCreateWithFlags(&g_evFork, cudaEventDisableTiming);
        cudaEventCreateWithFlags(&g_evJoin, cudaEventDisableTiming);
    }
} _g_init;
}

// ---------------------------------------------------------------------------
// 1) Histogram, 4 edges/thread (int4 loads, 4 independent REDs overlap)
// ---------------------------------------------------------------------------
__global__ __launch_bounds__(256) void hist_kernel(const int4* __restrict__ dst4,
                                                   int* __restrict__ cnt)
{
    int q = blockIdx.x * blockDim.x + threadIdx.x;
    if (q >= N_EDGES / 4) return;
    int4 d = __ldg(dst4 + q);
    atomicAdd(&cnt[d.x], 1);
    atomicAdd(&cnt[d.y], 1);
    atomicAdd(&cnt[d.z], 1);
    atomicAdd(&cnt[d.w], 1);
}

// ---------------------------------------------------------------------------
// 2) Merged scan: each block sums cnt[0..bid*256) for its base (L2-hot),
//    then scans its own 256 counters. scatter_idx re-zeroes cnt afterwards.
// ---------------------------------------------------------------------------
__global__ __launch_bounds__(256) void scanfin_kernel(
    const int* __restrict__ cnt, int* __restrict__ offs,
    int* __restrict__ cursor)
{
    __shared__ int sm[256];
    __shared__ int sbase[8];
    const int t = threadIdx.x;
    const int bid = blockIdx.x;

    const int4* cnt4 = (const int4*)cnt;
    int nq = bid * 64;
    int bv = 0;
    for (int i = t; i < nq; i += 256) {
        int4 v = __ldg(cnt4 + i);
        bv += (v.x + v.y) + (v.z + v.w);
    }
#pragma unroll
    for (int o = 16; o > 0; o >>= 1) bv += __shfl_down_sync(~0u, bv, o);
    if ((t & 31) == 0) sbase[t >> 5] = bv;

    int idx = bid * 256 + t;
    int c = (idx < N_NODES) ? __ldg(cnt + idx) : 0;
    sm[t] = c;
    __syncthreads();

    int base = sbase[0] + sbase[1] + sbase[2] + sbase[3] +
               sbase[4] + sbase[5] + sbase[6] + sbase[7];

    for (int off = 1; off < 256; off <<= 1) {
        int u = (t >= off) ? sm[t - off] : 0;
        __syncthreads();
        sm[t] += u;
        __syncthreads();
    }
    int off = base + sm[t] - c;   // exclusive prefix
    if (idx < N_NODES) {
        offs[idx]   = off;
        cursor[idx] = off;
        if (idx == N_NODES - 1) offs[N_NODES] = off + c;  // = N_EDGES
    }
}

// ---------------------------------------------------------------------------
// 3) Scatter, 4 edges/thread; also re-zeroes cnt for the next replay
// ---------------------------------------------------------------------------
__global__ __launch_bounds__(256) void scatter_idx_kernel(
    const int4* __restrict__ src4, const int4* __restrict__ dst4,
    int* __restrict__ cursor, int* __restrict__ sorted,
    int* __restrict__ cnt)
{
    int q = blockIdx.x * blockDim.x + threadIdx.x;
    if (q < N_NODES) cnt[q] = 0;              // replay reset (reads done)
    if (q >= N_EDGES / 4) return;
    int4 s = __ldg(src4 + q);
    int4 d = __ldg(dst4 + q);
    int p0 = atomicAdd(&cursor[d.x], 1);
    int p1 = atomicAdd(&cursor[d.y], 1);
    int p2 = atomicAdd(&cursor[d.z], 1);
    int p3 = atomicAdd(&cursor[d.w], 1);
    sorted[p0] = s.x;
    sorted[p1] = s.y;
    sorted[p2] = s.z;
    sorted[p3] = s.w;
}

// ---------------------------------------------------------------------------
// 4) Y = feat @ W^T, register-tiled along M (2 rows/thread):
//    128 threads/block = 4 warps; warp = 16-col quarter (W loads stay
//    whole-warp broadcast); lane = row; thread rows {lane, lane+32}.
//    Per kq: 16 W + 2 tile LDS feed 128 FFMA (ratio 7:1, was 4:1).
//    Tile lane-delta 17 f4 == 1 mod 8 -> conflict-free.
// ---------------------------------------------------------------------------
#define GR4 64   // rows per block

__global__ __launch_bounds__(128) void gemm_y_kernel(
    const float4* __restrict__ feat, const float4* __restrict__ W,
    float4* __restrict__ Y, uint2* __restrict__ Yh)
{
    __shared__ float4 Wsm[64 * 16];      // Wsm[j*16 + kq] = W[j][4kq..4kq+3]
    __shared__ float4 tile[GR4 * 17];    // padded row stride (conflict-free)

    const int tid  = threadIdx.x;
    const int row0 = blockIdx.x * GR4;

    for (int i = tid; i < 64 * 16; i += 128) Wsm[i] = W[i];
    for (int i = tid; i < GR4 * 16; i += 128) {
        int r = i >> 4, c = i & 15;
        int gr = row0 + r;
        float4 v = make_float4(0.f, 0.f, 0.f, 0.f);
        if (gr < N_NODES) v = feat[gr * 16 + c];
        tile[r * 17 + c] = v;
    }
    __syncthreads();

    const int lane = tid & 31;
    const int j0   = (tid >> 5) * 16;    // warp = 16-col quarter

    float acc0[16], acc1[16];
#pragma unroll
    for (int j = 0; j < 16; j++) { acc0[j] = 0.f; acc1[j] = 0.f; }

    for (int kq = 0; kq < 16; kq++) {
        float4 v0 = tile[lane * 17 + kq];          // row lane
        float4 v1 = tile[(lane + 32) * 17 + kq];   // row lane+32
#pragma unroll
        for (int j = 0; j < 16; j++) {
            float4 w = Wsm[(j0 + j) * 16 + kq];    // warp-broadcast
            acc0[j] += v0.x * w.x + v0.y * w.y + v0.z * w.z + v0.w * w.w;
            acc1[j] += v1.x * w.x + v1.y * w.y + v1.z * w.z + v1.w * w.w;
        }
    }

#pragma unroll
    for (int m = 0; m < 2; m++) {
        int gr = row0 + m * 32 + lane;
        if (gr < N_NODES) {
            float* acc = m ? acc1 : acc0;
#pragma unroll
            for (int q = 0; q < 4; q++) {
                float4 v = make_float4(acc[4 * q], acc[4 * q + 1],
                                       acc[4 * q + 2], acc[4 * q + 3]);
                int c = (j0 >> 2) + q;   // j0/4 .. j0/4+3  (4 float4 cols)
                Y[gr * 16 + c] = v;
                __half2 h0 = __floats2half2_rn(v.x, v.y);
                __half2 h1 = __floats2half2_rn(v.z, v.w);
                uint2 hp;
                hp.x = *(unsigned int*)&h0;
                hp.y = *(unsigned int*)&h1;
                Yh[gr * 16 + c] = hp;
            }
        }
    }
}

// ---------------------------------------------------------------------------
// 5) Final gather: out[g] = (1+eps)*Y[g] + sum_e Yh[src_e] + b
//    (proven: fp16 neighbor reads, fp32 accumulation + residual)
// ---------------------------------------------------------------------------
__global__ __launch_bounds__(256) void gather_final_kernel(
    const float4* __restrict__ Y, const uint2* __restrict__ Yh,
    const int* __restrict__ offs, const int* __restrict__ sorted,
    const float* __restrict__ eps, const float4* __restrict__ b4,
    float4* __restrict__ out)
{
    int g = (blockIdx.x * blockDim.x + threadIdx.x) >> 4;   // node
    int c = threadIdx.x & 15;
    if (g >= N_NODES) return;

    int beg = __ldg(offs + g);
    int end = __ldg(offs + g + 1);

    float4 a = make_float4(0.f, 0.f, 0.f, 0.f);
    int e = beg;
    for (; e + 4 <= end; e += 4) {
        int s0 = __ldg(sorted + e);
        int s1 = __ldg(sorted + e + 1);
        int s2 = __ldg(sorted + e + 2);
        int s3 = __ldg(sorted + e + 3);
        uint2 p0 = Yh[s0 * 16 + c];
        uint2 p1 = Yh[s1 * 16 + c];
        uint2 p2 = Yh[s2 * 16 + c];
        uint2 p3 = Yh[s3 * 16 + c];
        float2 f;
        f = __half22float2(*(__half2*)&p0.x); a.x += f.x; a.y += f.y;
        f = __half22float2(*(__half2*)&p0.y); a.z += f.x; a.w += f.y;
        f = __half22float2(*(__half2*)&p1.x); a.x += f.x; a.y += f.y;
        f = __half22float2(*(__half2*)&p1.y); a.z += f.x; a.w += f.y;
        f = __half22float2(*(__half2*)&p2.x); a.x += f.x; a.y += f.y;
        f = __half22float2(*(__half2*)&p2.y); a.z += f.x; a.w += f.y;
        f = __half22float2(*(__half2*)&p3.x); a.x += f.x; a.y += f.y;
        f = __half22float2(*(__half2*)&p3.y); a.z += f.x; a.w += f.y;
    }
    for (; e < end; e++) {
        int s = __ldg(sorted + e);
        uint2 p = Yh[s * 16 + c];
        float2 f;
        f = __half22float2(*(__half2*)&p.x); a.x += f.x; a.y += f.y;
        f = __half22float2(*(__half2*)&p.y); a.z += f.x; a.w += f.y;
    }

    float sc = 1.0f + __ldg(eps);
    float4 yg = Y[g * 16 + c];             // residual stays fp32
    float4 bb = __ldg(b4 + c);
    a.x += sc * yg.x + bb.x;
    a.y += sc * yg.y + bb.y;
    a.z += sc * yg.z + bb.z;
    a.w += sc * yg.w + bb.w;
    out[g * 16 + c] = a;
}

// ---------------------------------------------------------------------------
// Launch: inputs per metadata order: feat, W, b, eps, src, dst
// Fork: CSR build (side stream) overlaps GEMM (main stream).
// ---------------------------------------------------------------------------
extern "C" void kernel_launch(void* const* d_in, const int* in_sizes, int n_in,
                              void* d_out, int out_size)
{
    const float4* feat = (const float4*)d_in[0];
    const float4* W    = (const float4*)d_in[1];
    const float4* b4   = (const float4*)d_in[2];
    const float*  eps  = (const float*)d_in[3];
    const int4*   src4 = (const int4*)d_in[4];
    const int4*   dst4 = (const int4*)d_in[5];
    float4*       out  = (float4*)d_out;

    int *cnt, *offs, *cursor, *sorted;
    float* Y;
    __half* Yh;
    cudaGetSymbolAddress((void**)&cnt,    g_cnt);
    cudaGetSymbolAddress((void**)&offs,   g_offs);
    cudaGetSymbolAddress((void**)&cursor, g_cursor);
    cudaGetSymbolAddress((void**)&sorted, g_sorted);
    cudaGetSymbolAddress((void**)&Y,      g_Y);
    cudaGetSymbolAddress((void**)&Yh,     g_Yh);

    const int EQ = (N_EDGES / 4 + 255) / 256;   // 782 blocks, 4 edges/thread

    // Fork: CSR build chain on side stream
    cudaEventRecord(g_evFork, 0);
    cudaStreamWaitEvent(g_side, g_evFork, 0);
    hist_kernel<<<EQ, 256, 0, g_side>>>(dst4, cnt);
    scanfin_kernel<<<NBLK, 256, 0, g_side>>>(cnt, offs, cursor);
    scatter_idx_kernel<<<EQ, 256, 0, g_side>>>(src4, dst4, cursor, sorted, cnt);
    cudaEventRecord(g_evJoin, g_side);

    // Main stream: Y = feat @ W^T (+ fp16 copy), overlaps the CSR build
    {
        int blocks = (N_NODES + GR4 - 1) / GR4;   // 782
        gemm_y_kernel<<<blocks, 128>>>(feat, W, (float4*)Y, (uint2*)Yh);
    }

    // Join, then final gather writes out directly
    cudaStreamWaitEvent(0, g_evJoin, 0);
    {
        int threads = N_NODES * 16;
        gather_final_kernel<<<(threads + 255) / 256, 256>>>(
            (const float4*)Y, (const uint2*)Yh, offs, sorted, eps, b4, out);
    }
}

// round 14
// speedup vs baseline: 1.1307x; 1.1307x over previous
#include <cuda_runtime.h>
#include <cuda_bf16.h>
#include <cuda_fp16.h>

#define N_NODES 50000
#define N_EDGES 800000
#define D 64
#define NBLK ((N_NODES + 255) / 256)   // 196

// ---------------------------------------------------------------------------
// Static device scratch. g_cnt zero at load; scatter_idx re-zeroes it each
// run (after scanfin has consumed it) -> graph-replay deterministic.
// ---------------------------------------------------------------------------
__device__ int    g_cnt[N_NODES];
__device__ int    g_offs[N_NODES + 1];
__device__ int    g_cursor[N_NODES];
__device__ int    g_sorted[N_EDGES];
__device__ float  g_Y[N_NODES * D];            // Y = feat @ W^T (fp32)
__device__ __half g_Yh[N_NODES * D];           // fp16 copy for gather traffic

// Side stream + events for graph-forked overlap (created at program init).
static cudaStream_t g_side;
static cudaEvent_t  g_evFork, g_evJoin;
namespace {
struct _Init {
    _Init() {
        cudaStreamCreateWithFlags(&g_side, cudaStreamNonBlocking);
        cudaEventCreateWithFlags(&g_evFork, cudaEventDisableTiming);
        cudaEventCreateWithFlags(&g_evJoin, cudaEventDisableTiming);
    }
} _g_init;
}

// ---------------------------------------------------------------------------
// 1) Histogram, 4 edges/thread (int4 loads, 4 independent REDs overlap)
// ---------------------------------------------------------------------------
__global__ __launch_bounds__(256) void hist_kernel(const int4* __restrict__ dst4,
                                                   int* __restrict__ cnt)
{
    int q = blockIdx.x * blockDim.x + threadIdx.x;
    if (q >= N_EDGES / 4) return;
    int4 d = __ldg(dst4 + q);
    atomicAdd(&cnt[d.x], 1);
    atomicAdd(&cnt[d.y], 1);
    atomicAdd(&cnt[d.z], 1);
    atomicAdd(&cnt[d.w], 1);
}

// ---------------------------------------------------------------------------
// 2) Merged scan: each block sums cnt[0..bid*256) for its base (L2-hot),
//    then scans its own 256 counters. scatter_idx re-zeroes cnt afterwards.
// ---------------------------------------------------------------------------
__global__ __launch_bounds__(256) void scanfin_kernel(
    const int* __restrict__ cnt, int* __restrict__ offs,
    int* __restrict__ cursor)
{
    __shared__ int sm[256];
    __shared__ int sbase[8];
    const int t = threadIdx.x;
    const int bid = blockIdx.x;

    const int4* cnt4 = (const int4*)cnt;
    int nq = bid * 64;
    int bv = 0;
    for (int i = t; i < nq; i += 256) {
        int4 v = __ldg(cnt4 + i);
        bv += (v.x + v.y) + (v.z + v.w);
    }
#pragma unroll
    for (int o = 16; o > 0; o >>= 1) bv += __shfl_down_sync(~0u, bv, o);
    if ((t & 31) == 0) sbase[t >> 5] = bv;

    int idx = bid * 256 + t;
    int c = (idx < N_NODES) ? __ldg(cnt + idx) : 0;
    sm[t] = c;
    __syncthreads();

    int base = sbase[0] + sbase[1] + sbase[2] + sbase[3] +
               sbase[4] + sbase[5] + sbase[6] + sbase[7];

    for (int off = 1; off < 256; off <<= 1) {
        int u = (t >= off) ? sm[t - off] : 0;
        __syncthreads();
        sm[t] += u;
        __syncthreads();
    }
    int off = base + sm[t] - c;   // exclusive prefix
    if (idx < N_NODES) {
        offs[idx]   = off;
        cursor[idx] = off;
        if (idx == N_NODES - 1) offs[N_NODES] = off + c;  // = N_EDGES
    }
}

// ---------------------------------------------------------------------------
// 3) Scatter, 4 edges/thread; also re-zeroes cnt for the next replay
// ---------------------------------------------------------------------------
__global__ __launch_bounds__(256) void scatter_idx_kernel(
    const int4* __restrict__ src4, const int4* __restrict__ dst4,
    int* __restrict__ cursor, int* __restrict__ sorted,
    int* __restrict__ cnt)
{
    int q = blockIdx.x * blockDim.x + threadIdx.x;
    if (q < N_NODES) cnt[q] = 0;              // replay reset (reads done)
    if (q >= N_EDGES / 4) return;
    int4 s = __ldg(src4 + q);
    int4 d = __ldg(dst4 + q);
    int p0 = atomicAdd(&cursor[d.x], 1);
    int p1 = atomicAdd(&cursor[d.y], 1);
    int p2 = atomicAdd(&cursor[d.z], 1);
    int p3 = atomicAdd(&cursor[d.w], 1);
    sorted[p0] = s.x;
    sorted[p1] = s.y;
    sorted[p2] = s.z;
    sorted[p3] = s.w;
}

// ---------------------------------------------------------------------------
// Helpers for the tf32 tensor-core GEMM
// ---------------------------------------------------------------------------
__device__ __forceinline__ unsigned f2tf32(float a) {
    unsigned r;
    asm("cvt.rna.tf32.f32 %0, %1;" : "=r"(r) : "f"(a));
    return r;
}
__device__ __forceinline__ void split_tf32(float a, unsigned& hi, unsigned& lo) {
    hi = f2tf32(a);
    lo = f2tf32(a - __uint_as_float(hi));
}
__device__ __forceinline__ void mma_tf32(float* c, unsigned a0, unsigned a1,
                                         unsigned a2, unsigned a3,
                                         unsigned b0, unsigned b1) {
    asm("mma.sync.aligned.m16n8k8.row.col.f32.tf32.tf32.f32 "
        "{%0,%1,%2,%3}, {%4,%5,%6,%7}, {%8,%9}, {%0,%1,%2,%3};"
        : "+f"(c[0]), "+f"(c[1]), "+f"(c[2]), "+f"(c[3])
        : "r"(a0), "r"(a1), "r"(a2), "r"(a3), "r"(b0), "r"(b1));
}

// ---------------------------------------------------------------------------
// 4) Y = feat @ W^T via mma.sync m16n8k8 tf32 with 3xTF32 split (~fp32 acc).
//    128 threads = 4 warps; each warp: 16 rows x 64 cols; 64 rows/block.
//    Smem float-row-stride 68 (== 4 mod 32): fragment lanes (g,tig) map to
//    banks 4g+tig -> all 32 distinct, conflict-free.
// ---------------------------------------------------------------------------
#define GR5 64   // rows per block

__global__ __launch_bounds__(128) void gemm_y_kernel(
    const float4* __restrict__ feat, const float4* __restrict__ W4,
    float* __restrict__ Y, __half2* __restrict__ Yh)
{
    __shared__ float tile[GR5 * 68];   // feat rows, stride 68 floats
    __shared__ float Wsm[64 * 68];     // W rows,   stride 68 floats

    const int tid  = threadIdx.x;
    const int row0 = blockIdx.x * GR5;

    // Stage W: float4 into stride-68 rows (68*4B % 16 == 0 -> aligned)
    for (int i = tid; i < 64 * 16; i += 128) {
        int j = i >> 4, c = i & 15;
        ((float4*)(Wsm + j * 68))[c] = W4[i];
    }
    // Stage feat tile
    for (int i = tid; i < GR5 * 16; i += 128) {
        int r = i >> 4, c = i & 15;
        int gr = row0 + r;
        float4 v = make_float4(0.f, 0.f, 0.f, 0.f);
        if (gr < N_NODES) v = feat[gr * 16 + c];
        ((float4*)(tile + r * 68))[c] = v;
    }
    __syncthreads();

    const int warp = tid >> 5;
    const int lane = tid & 31;
    const int g    = lane >> 2;      // 0..7
    const int tg   = lane & 3;       // 0..3
    const int r0   = warp * 16;      // warp's 16-row group

    float acc[8][4];
#pragma unroll
    for (int jt = 0; jt < 8; jt++)
#pragma unroll
        for (int q = 0; q < 4; q++) acc[jt][q] = 0.f;

    for (int kt = 0; kt < 8; kt++) {
        // A fragment (rows g / g+8, cols kt*8 + tg / tg+4), hi/lo split
        float fa0 = tile[(r0 + g) * 68 + kt * 8 + tg];
        float fa1 = tile[(r0 + g + 8) * 68 + kt * 8 + tg];
        float fa2 = tile[(r0 + g) * 68 + kt * 8 + tg + 4];
        float fa3 = tile[(r0 + g + 8) * 68 + kt * 8 + tg + 4];
        unsigned ah0, al0, ah1, al1, ah2, al2, ah3, al3;
        split_tf32(fa0, ah0, al0);
        split_tf32(fa1, ah1, al1);
        split_tf32(fa2, ah2, al2);
        split_tf32(fa3, ah3, al3);

#pragma unroll
        for (int jt = 0; jt < 8; jt++) {
            // B fragment: W[jt*8+g][kt*8+tg(,+4)]  (n=col-major k x n)
            float fb0 = Wsm[(jt * 8 + g) * 68 + kt * 8 + tg];
            float fb1 = Wsm[(jt * 8 + g) * 68 + kt * 8 + tg + 4];
            unsigned bh0, bl0, bh1, bl1;
            split_tf32(fb0, bh0, bl0);
            split_tf32(fb1, bh1, bl1);

            // 3xTF32: hi*hi + hi*lo + lo*hi
            mma_tf32(acc[jt], ah0, ah1, ah2, ah3, bh0, bh1);
            mma_tf32(acc[jt], ah0, ah1, ah2, ah3, bl0, bl1);
            mma_tf32(acc[jt], al0, al1, al2, al3, bh0, bh1);
        }
    }

    // Epilogue: c0,c1 -> (row g, cols 2tg,2tg+1); c2,c3 -> row g+8
#pragma unroll
    for (int jt = 0; jt < 8; jt++) {
        int col = jt * 8 + 2 * tg;
        int rA = row0 + r0 + g;
        int rB = rA + 8;
        if (rA < N_NODES) {
            float2 v = make_float2(acc[jt][0], acc[jt][1]);
            *(float2*)(Y + rA * 64 + col) = v;
            Yh[(rA * 64 + col) >> 1] = __floats2half2_rn(v.x, v.y);
        }
        if (rB < N_NODES) {
            float2 v = make_float2(acc[jt][2], acc[jt][3]);
            *(float2*)(Y + rB * 64 + col) = v;
            Yh[(rB * 64 + col) >> 1] = __floats2half2_rn(v.x, v.y);
        }
    }
}

// ---------------------------------------------------------------------------
// 5) Final gather: out[g] = (1+eps)*Y[g] + sum_e Yh[src_e] + b
//    (proven: fp16 neighbor reads, fp32 accumulation + residual)
// ---------------------------------------------------------------------------
__global__ __launch_bounds__(256) void gather_final_kernel(
    const float4* __restrict__ Y, const uint2* __restrict__ Yh,
    const int* __restrict__ offs, const int* __restrict__ sorted,
    const float* __restrict__ eps, const float4* __restrict__ b4,
    float4* __restrict__ out)
{
    int g = (blockIdx.x * blockDim.x + threadIdx.x) >> 4;   // node
    int c = threadIdx.x & 15;
    if (g >= N_NODES) return;

    int beg = __ldg(offs + g);
    int end = __ldg(offs + g + 1);

    float4 a = make_float4(0.f, 0.f, 0.f, 0.f);
    int e = beg;
    for (; e + 4 <= end; e += 4) {
        int s0 = __ldg(sorted + e);
        int s1 = __ldg(sorted + e + 1);
        int s2 = __ldg(sorted + e + 2);
        int s3 = __ldg(sorted + e + 3);
        uint2 p0 = Yh[s0 * 16 + c];
        uint2 p1 = Yh[s1 * 16 + c];
        uint2 p2 = Yh[s2 * 16 + c];
        uint2 p3 = Yh[s3 * 16 + c];
        float2 f;
        f = __half22float2(*(__half2*)&p0.x); a.x += f.x; a.y += f.y;
        f = __half22float2(*(__half2*)&p0.y); a.z += f.x; a.w += f.y;
        f = __half22float2(*(__half2*)&p1.x); a.x += f.x; a.y += f.y;
        f = __half22float2(*(__half2*)&p1.y); a.z += f.x; a.w += f.y;
        f = __half22float2(*(__half2*)&p2.x); a.x += f.x; a.y += f.y;
        f = __half22float2(*(__half2*)&p2.y); a.z += f.x; a.w += f.y;
        f = __half22float2(*(__half2*)&p3.x); a.x += f.x; a.y += f.y;
        f = __half22float2(*(__half2*)&p3.y); a.z += f.x; a.w += f.y;
    }
    for (; e < end; e++) {
        int s = __ldg(sorted + e);
        uint2 p = Yh[s * 16 + c];
        float2 f;
        f = __half22float2(*(__half2*)&p.x); a.x += f.x; a.y += f.y;
        f = __half22float2(*(__half2*)&p.y); a.z += f.x; a.w += f.y;
    }

    float sc = 1.0f + __ldg(eps);
    float4 yg = Y[g * 16 + c];             // residual stays fp32
    float4 bb = __ldg(b4 + c);
    a.x += sc * yg.x + bb.x;
    a.y += sc * yg.y + bb.y;
    a.z += sc * yg.z + bb.z;
    a.w += sc * yg.w + bb.w;
    out[g * 16 + c] = a;
}

// ---------------------------------------------------------------------------
// Launch: inputs per metadata order: feat, W, b, eps, src, dst
// Fork: CSR build (side stream) overlaps GEMM (main stream).
// ---------------------------------------------------------------------------
extern "C" void kernel_launch(void* const* d_in, const int* in_sizes, int n_in,
                              void* d_out, int out_size)
{
    const float4* feat = (const float4*)d_in[0];
    const float4* W    = (const float4*)d_in[1];
    const float4* b4   = (const float4*)d_in[2];
    const float*  eps  = (const float*)d_in[3];
    const int4*   src4 = (const int4*)d_in[4];
    const int4*   dst4 = (const int4*)d_in[5];
    float4*       out  = (float4*)d_out;

    int *cnt, *offs, *cursor, *sorted;
    float* Y;
    __half* Yh;
    cudaGetSymbolAddress((void**)&cnt,    g_cnt);
    cudaGetSymbolAddress((void**)&offs,   g_offs);
    cudaGetSymbolAddress((void**)&cursor, g_cursor);
    cudaGetSymbolAddress((void**)&sorted, g_sorted);
    cudaGetSymbolAddress((void**)&Y,      g_Y);
    cudaGetSymbolAddress((void**)&Yh,     g_Yh);

    const int EQ = (N_EDGES / 4 + 255) / 256;   // 782 blocks, 4 edges/thread

    // Fork: CSR build chain on side stream
    cudaEventRecord(g_evFork, 0);
    cudaStreamWaitEvent(g_side, g_evFork, 0);
    hist_kernel<<<EQ, 256, 0, g_side>>>(dst4, cnt);
    scanfin_kernel<<<NBLK, 256, 0, g_side>>>(cnt, offs, cursor);
    scatter_idx_kernel<<<EQ, 256, 0, g_side>>>(src4, dst4, cursor, sorted, cnt);
    cudaEventRecord(g_evJoin, g_side);

    // Main stream: Y = feat @ W^T (tensor cores), overlaps the CSR build
    {
        int blocks = (N_NODES + GR5 - 1) / GR5;   // 782
        gemm_y_kernel<<<blocks, 128>>>(feat, W, Y, (__half2*)Yh);
    }

    // Join, then final gather writes out directly
    cudaStreamWaitEvent(0, g_evJoin, 0);
    {
        int threads = N_NODES * 16;
        gather_final_kernel<<<(threads + 255) / 256, 256>>>(
            (const float4*)Y, (const uint2*)Yh, offs, sorted, eps, b4, out);
    }
}